// round 1
// baseline (speedup 1.0000x reference)
#include <cuda_runtime.h>
#include <cuda_bf16.h>
#include <cstdint>

#define N_NODES 100000
#define N_EDGES 2000000
#define DIM 64

// Scratch (no cudaMalloc allowed): agg buffer, layer-1 hidden, degree.
__device__ __align__(16) float g_agg[(size_t)N_NODES * DIM];
__device__ __align__(16) float g_h1[(size_t)N_NODES * DIM];
__device__ float g_deg[N_NODES];

// ---------------------------------------------------------------------------
// Scatter: agg[dst] += h[src] for every edge. 16 threads per edge, each moving
// one float4 (16B) via vectorized no-return reduction (red.global.add.v4.f32).
// Optionally also accumulates the in-degree (layer 0 only).
// ---------------------------------------------------------------------------
template <bool COUNT_DEG>
__global__ void __launch_bounds__(256)
scatter_kernel(const float* __restrict__ h, const int* __restrict__ ei)
{
    unsigned tid = blockIdx.x * blockDim.x + threadIdx.x;
    unsigned e = tid >> 4;       // edge id
    unsigned c = tid & 15;       // float4 chunk within the 64-dim row
    if (e >= N_EDGES) return;

    int src = ei[e];
    int dst = ei[N_EDGES + e];

    const float4* __restrict__ h4 = reinterpret_cast<const float4*>(h);
    float4 v = h4[(size_t)src * 16 + c];

    float* addr = g_agg + (size_t)dst * DIM + (size_t)c * 4;
    asm volatile("red.global.add.v4.f32 [%0], {%1, %2, %3, %4};"
                 :: "l"(addr), "f"(v.x), "f"(v.y), "f"(v.z), "f"(v.w)
                 : "memory");

    if (COUNT_DEG && c == 0) {
        atomicAdd(&g_deg[dst], 1.0f);
    }
}

// ---------------------------------------------------------------------------
// Transform: out[node] = act( concat(h[node], agg[node]*inv_deg) @ W + b )
// Warp per node. Each lane holds 4 of the 128 input values; shuffle-broadcast
// each input and FMA against W rows held in shared memory. Each lane produces
// output dims {lane, lane+32}.
// W layout: [128 in][64 out], row-major (y = x @ W + b).
// ---------------------------------------------------------------------------
template <bool RELU>
__global__ void __launch_bounds__(256)
transform_kernel(const float* __restrict__ h,
                 const float* __restrict__ W,
                 const float* __restrict__ b,
                 float* __restrict__ out)
{
    __shared__ float Ws[128 * 64];
    __shared__ float bs[64];

    for (int i = threadIdx.x; i < 128 * 64; i += blockDim.x) Ws[i] = W[i];
    if (threadIdx.x < 64) bs[threadIdx.x] = b[threadIdx.x];
    __syncthreads();

    int lane = threadIdx.x & 31;
    int warp = threadIdx.x >> 5;
    int node = blockIdx.x * (blockDim.x >> 5) + warp;
    if (node >= N_NODES) return;

    float inv = 1.0f / fmaxf(g_deg[node], 1.0f);

    const float* hrow = h + (size_t)node * DIM;
    const float* arow = g_agg + (size_t)node * DIM;

    // 4 input values per lane: rows [0..31],[32..63] from h, [64..95],[96..127] from agg.
    float v0 = hrow[lane];
    float v1 = hrow[32 + lane];
    float v2 = arow[lane] * inv;
    float v3 = arow[32 + lane] * inv;

    float acc0 = bs[lane];
    float acc1 = bs[32 + lane];

    #pragma unroll
    for (int i = 0; i < 32; i++) {
        float t = __shfl_sync(0xffffffffu, v0, i);
        acc0 = fmaf(t, Ws[i * 64 + lane], acc0);
        acc1 = fmaf(t, Ws[i * 64 + 32 + lane], acc1);
    }
    #pragma unroll
    for (int i = 0; i < 32; i++) {
        float t = __shfl_sync(0xffffffffu, v1, i);
        acc0 = fmaf(t, Ws[(32 + i) * 64 + lane], acc0);
        acc1 = fmaf(t, Ws[(32 + i) * 64 + 32 + lane], acc1);
    }
    #pragma unroll
    for (int i = 0; i < 32; i++) {
        float t = __shfl_sync(0xffffffffu, v2, i);
        acc0 = fmaf(t, Ws[(64 + i) * 64 + lane], acc0);
        acc1 = fmaf(t, Ws[(64 + i) * 64 + 32 + lane], acc1);
    }
    #pragma unroll
    for (int i = 0; i < 32; i++) {
        float t = __shfl_sync(0xffffffffu, v3, i);
        acc0 = fmaf(t, Ws[(96 + i) * 64 + lane], acc0);
        acc1 = fmaf(t, Ws[(96 + i) * 64 + 32 + lane], acc1);
    }

    if (RELU) {
        acc0 = fmaxf(acc0, 0.0f);
        acc1 = fmaxf(acc1, 0.0f);
    }

    out[(size_t)node * DIM + lane] = acc0;
    out[(size_t)node * DIM + 32 + lane] = acc1;
}

extern "C" void kernel_launch(void* const* d_in, const int* in_sizes, int n_in,
                              void* d_out, int out_size)
{
    const float* x  = (const float*)d_in[0];
    const int*   ei = (const int*)  d_in[1];
    const float* W0 = (const float*)d_in[2];
    const float* b0 = (const float*)d_in[3];
    const float* W1 = (const float*)d_in[4];
    const float* b1 = (const float*)d_in[5];
    float* out = (float*)d_out;

    void *agg_ptr = nullptr, *h1_ptr = nullptr, *deg_ptr = nullptr;
    cudaGetSymbolAddress(&agg_ptr, g_agg);
    cudaGetSymbolAddress(&h1_ptr,  g_h1);
    cudaGetSymbolAddress(&deg_ptr, g_deg);
    float* h1 = (float*)h1_ptr;

    const size_t agg_bytes = (size_t)N_NODES * DIM * sizeof(float);

    const int scatter_threads = N_EDGES * 16;
    const int scatter_blocks  = (scatter_threads + 255) / 256;
    const int xform_blocks    = (N_NODES + 7) / 8;   // 8 nodes per 256-thread block

    // ---- Layer 0 ----
    cudaMemsetAsync(agg_ptr, 0, agg_bytes);
    cudaMemsetAsync(deg_ptr, 0, N_NODES * sizeof(float));
    scatter_kernel<true><<<scatter_blocks, 256>>>(x, ei);
    transform_kernel<true><<<xform_blocks, 256>>>(x, W0, b0, h1);

    // ---- Layer 1 ----
    cudaMemsetAsync(agg_ptr, 0, agg_bytes);
    scatter_kernel<false><<<scatter_blocks, 256>>>(h1, ei);
    transform_kernel<false><<<xform_blocks, 256>>>(h1, W1, b1, out);
}

// round 2
// speedup vs baseline: 1.4436x; 1.4436x over previous
#include <cuda_runtime.h>
#include <cuda_bf16.h>
#include <cstdint>

#define N_NODES 100000
#define N_EDGES 2000000
#define DIM 64

// Scratch (no cudaMalloc allowed): agg buffer, layer-1 hidden, degree.
__device__ __align__(16) float g_agg[(size_t)N_NODES * DIM];
__device__ __align__(16) float g_h1[(size_t)N_NODES * DIM];
__device__ float g_deg[N_NODES];

// ---------------------------------------------------------------------------
// Scatter: agg[dst] += h[src] for every edge. 16 threads per edge, each moving
// one float4 (16B) via vectorized no-return reduction (red.global.add.v4.f32).
// Optionally also accumulates the in-degree (layer 0 only).
// ---------------------------------------------------------------------------
template <bool COUNT_DEG>
__global__ void __launch_bounds__(256)
scatter_kernel(const float* __restrict__ h, const int* __restrict__ ei)
{
    unsigned tid = blockIdx.x * blockDim.x + threadIdx.x;
    unsigned e = tid >> 4;       // edge id
    unsigned c = tid & 15;       // float4 chunk within the 64-dim row
    if (e >= N_EDGES) return;

    int src = ei[e];
    int dst = ei[N_EDGES + e];

    const float4* __restrict__ h4 = reinterpret_cast<const float4*>(h);
    float4 v = h4[(size_t)src * 16 + c];

    float* addr = g_agg + (size_t)dst * DIM + (size_t)c * 4;
    asm volatile("red.global.add.v4.f32 [%0], {%1, %2, %3, %4};"
                 :: "l"(addr), "f"(v.x), "f"(v.y), "f"(v.z), "f"(v.w)
                 : "memory");

    if (COUNT_DEG && c == 0) {
        atomicAdd(&g_deg[dst], 1.0f);
    }
}

// ---------------------------------------------------------------------------
// Transform: out[node] = act( concat(h[node], agg[node]*inv_deg) @ W + b )
// 4 nodes per warp. Lane l produces output dims {l, l+32} for each of the 4
// nodes. W staged in shared as interleaved float2 so the pair of weights a
// lane needs per input-row is ONE LDS.64, amortized over 4 nodes (8 FFMA).
// Inputs are broadcast from registers via shfl.
// W layout: [128 in][64 out], row-major (y = x @ W + b).
// ---------------------------------------------------------------------------
template <bool RELU>
__global__ void __launch_bounds__(256)
transform_kernel(const float* __restrict__ h,
                 const float* __restrict__ W,
                 const float* __restrict__ b,
                 float* __restrict__ out)
{
    __shared__ float2 Ws2[128 * 32];   // Ws2[i*32+l] = { W[i][l], W[i][l+32] }
    __shared__ float bs[64];

    for (int idx = threadIdx.x; idx < 128 * 64; idx += 256) {
        int i = idx >> 6;
        int col = idx & 63;
        float v = W[idx];
        if (col < 32) Ws2[i * 32 + col].x = v;
        else          Ws2[i * 32 + (col - 32)].y = v;
    }
    if (threadIdx.x < 64) bs[threadIdx.x] = b[threadIdx.x];
    __syncthreads();

    const int lane  = threadIdx.x & 31;
    const int warp  = threadIdx.x >> 5;
    const int node0 = (blockIdx.x * 8 + warp) * 4;   // grid sized exactly

    float v0[4], v1[4], v2[4], v3[4], acc0[4], acc1[4];

    #pragma unroll
    for (int j = 0; j < 4; j++) {
        int node = node0 + j;
        float inv = 1.0f / fmaxf(g_deg[node], 1.0f);
        const float* hr = h     + (size_t)node * DIM;
        const float* ar = g_agg + (size_t)node * DIM;
        v0[j] = hr[lane];
        v1[j] = hr[32 + lane];
        v2[j] = ar[lane] * inv;
        v3[j] = ar[32 + lane] * inv;
        acc0[j] = bs[lane];
        acc1[j] = bs[32 + lane];
    }

    // Input rows 0..31 (v0)
    #pragma unroll
    for (int i = 0; i < 32; i++) {
        float2 w = Ws2[i * 32 + lane];
        #pragma unroll
        for (int j = 0; j < 4; j++) {
            float t = __shfl_sync(0xffffffffu, v0[j], i);
            acc0[j] = fmaf(t, w.x, acc0[j]);
            acc1[j] = fmaf(t, w.y, acc1[j]);
        }
    }
    // Input rows 32..63 (v1)
    #pragma unroll
    for (int i = 0; i < 32; i++) {
        float2 w = Ws2[(32 + i) * 32 + lane];
        #pragma unroll
        for (int j = 0; j < 4; j++) {
            float t = __shfl_sync(0xffffffffu, v1[j], i);
            acc0[j] = fmaf(t, w.x, acc0[j]);
            acc1[j] = fmaf(t, w.y, acc1[j]);
        }
    }
    // Input rows 64..95 (v2 = agg * inv_deg)
    #pragma unroll
    for (int i = 0; i < 32; i++) {
        float2 w = Ws2[(64 + i) * 32 + lane];
        #pragma unroll
        for (int j = 0; j < 4; j++) {
            float t = __shfl_sync(0xffffffffu, v2[j], i);
            acc0[j] = fmaf(t, w.x, acc0[j]);
            acc1[j] = fmaf(t, w.y, acc1[j]);
        }
    }
    // Input rows 96..127 (v3)
    #pragma unroll
    for (int i = 0; i < 32; i++) {
        float2 w = Ws2[(96 + i) * 32 + lane];
        #pragma unroll
        for (int j = 0; j < 4; j++) {
            float t = __shfl_sync(0xffffffffu, v3[j], i);
            acc0[j] = fmaf(t, w.x, acc0[j]);
            acc1[j] = fmaf(t, w.y, acc1[j]);
        }
    }

    #pragma unroll
    for (int j = 0; j < 4; j++) {
        float a0 = acc0[j], a1 = acc1[j];
        if (RELU) { a0 = fmaxf(a0, 0.0f); a1 = fmaxf(a1, 0.0f); }
        size_t base = (size_t)(node0 + j) * DIM;
        out[base + lane]      = a0;
        out[base + 32 + lane] = a1;
    }
}

extern "C" void kernel_launch(void* const* d_in, const int* in_sizes, int n_in,
                              void* d_out, int out_size)
{
    const float* x  = (const float*)d_in[0];
    const int*   ei = (const int*)  d_in[1];
    const float* W0 = (const float*)d_in[2];
    const float* b0 = (const float*)d_in[3];
    const float* W1 = (const float*)d_in[4];
    const float* b1 = (const float*)d_in[5];
    float* out = (float*)d_out;

    void *agg_ptr = nullptr, *h1_ptr = nullptr, *deg_ptr = nullptr;
    cudaGetSymbolAddress(&agg_ptr, g_agg);
    cudaGetSymbolAddress(&h1_ptr,  g_h1);
    cudaGetSymbolAddress(&deg_ptr, g_deg);
    float* h1 = (float*)h1_ptr;

    const size_t agg_bytes = (size_t)N_NODES * DIM * sizeof(float);

    const int scatter_threads = N_EDGES * 16;
    const int scatter_blocks  = (scatter_threads + 255) / 256;
    const int xform_blocks    = N_NODES / 32;   // 32 nodes per block, exact

    // ---- Layer 0 ----
    cudaMemsetAsync(agg_ptr, 0, agg_bytes);
    cudaMemsetAsync(deg_ptr, 0, N_NODES * sizeof(float));
    scatter_kernel<true><<<scatter_blocks, 256>>>(x, ei);
    transform_kernel<true><<<xform_blocks, 256>>>(x, W0, b0, h1);

    // ---- Layer 1 ----
    cudaMemsetAsync(agg_ptr, 0, agg_bytes);
    scatter_kernel<false><<<scatter_blocks, 256>>>(h1, ei);
    transform_kernel<false><<<xform_blocks, 256>>>(h1, W1, b1, out);
}